// round 14
// baseline (speedup 1.0000x reference)
#include <cuda_runtime.h>

// Complex BatchNorm, B=16, OUTPUT = float32 REAL PART ONLY.
// R14 experiment: hybrid access width. 64-bit LOADS (asm-pinned ld.v2 so
// ptxas cannot fuse adjacent pairs into 128-bit) + 128-bit STORES (st.v4).
// 4 positions/thread. Tests whether R6/R11's 128-bit slowdown came from the
// loads (wavefront replays) or the stores. Fallback = proven R8 kernel.

#define EPS 1e-5f

__device__ __forceinline__ float2 ldg64(const float2* p) {
    float2 v;
    asm volatile("ld.global.nc.v2.f32 {%0, %1}, [%2];"
                 : "=f"(v.x), "=f"(v.y) : "l"(p));
    return v;
}

__global__ __launch_bounds__(256) void cbn_b16_h_kernel(
    const float2* __restrict__ x_real,   // viewed as float2 array, length 2*n4 per batch... (indexed explicitly)
    const float2* __restrict__ x_imag,
    const float2* __restrict__ g_rr,
    const float2* __restrict__ g_ri,
    const float2* __restrict__ beta,
    float4* __restrict__ out,
    int n4)   // n/4 ; float2 view has 2*n4 elements per batch row
{
    int idx = blockIdx.x * blockDim.x + threadIdx.x;
    if (idx >= n4) return;

    const long long n2 = 2LL * n4;       // float2 elements per batch row

    // two float2 slots per thread: 2*idx and 2*idx+1 (4 consecutive floats)
    float2 rvA[16], rvB[16], ivA[16], ivB[16];
    #pragma unroll
    for (int b = 0; b < 16; b++) {
        const float2* pr = x_real + (size_t)b * n2 + 2 * idx;
        const float2* pi = x_imag + (size_t)b * n2 + 2 * idx;
        rvA[b] = ldg64(pr);
        rvB[b] = ldg64(pr + 1);
        ivA[b] = ldg64(pi);
        ivB[b] = ldg64(pi + 1);
    }

    float2 grrA = g_rr[2 * idx], grrB = g_rr[2 * idx + 1];
    float2 griA = g_ri[2 * idx], griB = g_ri[2 * idx + 1];
    float2 btA  = beta[2 * idx], btB  = beta[2 * idx + 1];

    const float inv_b = 1.0f / 16.0f;

    // process 4 lanes: (A.x, A.y, B.x, B.y)
    #pragma unroll
    for (int lane = 0; lane < 4; lane++) {
        const bool useB = lane >= 2;
        const int c = lane & 1;

        float sr = 0.f, si = 0.f;
        #pragma unroll
        for (int b = 0; b < 16; b++) {
            float r = useB ? ((const float*)&rvB[b])[c] : ((const float*)&rvA[b])[c];
            float i = useB ? ((const float*)&ivB[b])[c] : ((const float*)&ivA[b])[c];
            sr += r; si += i;
        }
        float mu_r = sr * inv_b, mu_i = si * inv_b;

        float vrr = 0.f, vii = 0.f, vri = 0.f;
        #pragma unroll
        for (int b = 0; b < 16; b++) {
            float r = useB ? ((const float*)&rvB[b])[c] : ((const float*)&rvA[b])[c];
            float i = useB ? ((const float*)&ivB[b])[c] : ((const float*)&ivA[b])[c];
            float rc = r - mu_r, ic = i - mu_i;
            vrr = fmaf(rc, rc, vrr);
            vii = fmaf(ic, ic, vii);
            vri = fmaf(rc, ic, vri);
        }
        vrr = vrr * inv_b + EPS;
        vii = vii * inv_b + EPS;
        vri = vri * inv_b;

        float s = sqrtf(fmaf(vrr, vii, -vri * vri));
        float t = sqrtf(vrr + vii + 2.0f * s);
        float inv_st = 1.0f / (s * t);
        float wrr = (vii + s) * inv_st;
        float wii = (vrr + s) * inv_st;
        float wri = -vri * inv_st;

        float grr = useB ? ((const float*)&grrB)[c] : ((const float*)&grrA)[c];
        float gri = useB ? ((const float*)&griB)[c] : ((const float*)&griA)[c];
        float bt  = useB ? ((const float*)&btB)[c]  : ((const float*)&btA)[c];

        #pragma unroll
        for (int b = 0; b < 16; b++) {
            float r = useB ? ((const float*)&rvB[b])[c] : ((const float*)&rvA[b])[c];
            float i = useB ? ((const float*)&ivB[b])[c] : ((const float*)&ivA[b])[c];
            float rc = r - mu_r, ic = i - mu_i;
            float nr = fmaf(wrr, rc, wri * ic);
            float ni = fmaf(wii, ic, wri * rc);
            float res = fmaf(grr, nr, fmaf(gri, ni, bt));
            if (useB) ((float*)&rvB[b])[c] = res;
            else      ((float*)&rvA[b])[c] = res;
        }
    }

    #pragma unroll
    for (int b = 0; b < 16; b++) {
        float4 o;
        o.x = rvA[b].x; o.y = rvA[b].y; o.z = rvB[b].x; o.w = rvB[b].y;
        out[(size_t)b * n4 + idx] = o;   // single STG.128 per batch
    }
}

// ---------- proven R8 kernel (fallback / revert target) ----------

__global__ __launch_bounds__(256) void cbn_b16_v2_kernel(
    const float2* __restrict__ x_real,
    const float2* __restrict__ x_imag,
    const float2* __restrict__ g_rr,
    const float2* __restrict__ g_ri,
    const float2* __restrict__ beta,
    float2* __restrict__ out,
    int n2)
{
    int idx = blockIdx.x * blockDim.x + threadIdx.x;
    if (idx >= n2) return;

    float2 rv[16], iv[16];
    #pragma unroll
    for (int b = 0; b < 16; b++) {
        rv[b] = x_real[(size_t)b * n2 + idx];
        iv[b] = x_imag[(size_t)b * n2 + idx];
    }

    float2 grr2 = g_rr[idx];
    float2 gri2 = g_ri[idx];
    float2 bt2  = beta[idx];
    const float inv_b = 1.0f / 16.0f;

    #pragma unroll
    for (int lane = 0; lane < 2; lane++) {
        float sr = 0.f, si = 0.f;
        #pragma unroll
        for (int b = 0; b < 16; b++) {
            sr += ((const float*)&rv[b])[lane];
            si += ((const float*)&iv[b])[lane];
        }
        float mu_r = sr * inv_b, mu_i = si * inv_b;

        float vrr = 0.f, vii = 0.f, vri = 0.f;
        #pragma unroll
        for (int b = 0; b < 16; b++) {
            float rc = ((const float*)&rv[b])[lane] - mu_r;
            float ic = ((const float*)&iv[b])[lane] - mu_i;
            vrr = fmaf(rc, rc, vrr);
            vii = fmaf(ic, ic, vii);
            vri = fmaf(rc, ic, vri);
        }
        vrr = vrr * inv_b + EPS;
        vii = vii * inv_b + EPS;
        vri = vri * inv_b;

        float s   = sqrtf(fmaf(vrr, vii, -vri * vri));
        float t   = sqrtf(vrr + vii + 2.0f * s);
        float inv_st = 1.0f / (s * t);
        float wrr = (vii + s) * inv_st;
        float wii = (vrr + s) * inv_st;
        float wri = -vri * inv_st;

        float grr = ((const float*)&grr2)[lane];
        float gri = ((const float*)&gri2)[lane];
        float bt  = ((const float*)&bt2)[lane];

        #pragma unroll
        for (int b = 0; b < 16; b++) {
            float rc = ((const float*)&rv[b])[lane] - mu_r;
            float ic = ((const float*)&iv[b])[lane] - mu_i;
            float nr = fmaf(wrr, rc, wri * ic);
            float ni = fmaf(wii, ic, wri * rc);
            ((float*)&rv[b])[lane] = fmaf(grr, nr, fmaf(gri, ni, bt));
        }
    }

    #pragma unroll
    for (int b = 0; b < 16; b++)
        out[(size_t)b * n2 + idx] = rv[b];
}

// ---------- generic fallback ----------

template <int MODE>
__global__ __launch_bounds__(256) void cbn_gen_kernel(
    const float* __restrict__ x_real,
    const float* __restrict__ x_imag,
    const float* __restrict__ g_rr,
    const float* __restrict__ g_ri,
    const float* __restrict__ g_ii,
    const float* __restrict__ beta,
    float* __restrict__ out_f,
    int n, int B, long long out_cap)
{
    int idx = blockIdx.x * blockDim.x + threadIdx.x;
    if (idx >= n) return;

    float sr = 0.f, si = 0.f, srr = 0.f, sii = 0.f, sri = 0.f;
    for (int b = 0; b < B; b++) {
        float rvv = x_real[(size_t)b * n + idx];
        float ivv = x_imag[(size_t)b * n + idx];
        sr += rvv; si += ivv;
        srr = fmaf(rvv, rvv, srr);
        sii = fmaf(ivv, ivv, sii);
        sri = fmaf(rvv, ivv, sri);
    }
    float inv_b = 1.0f / (float)B;
    float mu_r = sr * inv_b, mu_i = si * inv_b;
    float vrr = srr * inv_b - mu_r * mu_r + EPS;
    float vii = sii * inv_b - mu_i * mu_i + EPS;
    float vri = sri * inv_b - mu_r * mu_i;

    float s   = sqrtf(fmaf(vrr, vii, -vri * vri));
    float t   = sqrtf(vrr + vii + 2.0f * s);
    float inv_st = 1.0f / (s * t);
    float wrr = (vii + s) * inv_st;
    float wii = (vrr + s) * inv_st;
    float wri = -vri * inv_st;

    float grr = g_rr[idx], gri = g_ri[idx], gii = g_ii[idx], bt = beta[idx];

    for (int b = 0; b < B; b++) {
        float rc = x_real[(size_t)b * n + idx] - mu_r;
        float ic = x_imag[(size_t)b * n + idx] - mu_i;
        float nr = fmaf(wrr, rc, wri * ic);
        float ni = fmaf(wii, ic, wri * rc);
        float re = fmaf(grr, nr, fmaf(gri, ni, bt));
        long long j = (long long)b * n + idx;
        if (MODE == 0) {
            if (j < out_cap) out_f[j] = re;
        } else {
            float ie = fmaf(gri, nr, fmaf(gii, ni, bt));
            long long f = 2 * j;
            if (f + 1 < out_cap) {
                float2 o; o.x = re; o.y = ie;
                *reinterpret_cast<float2*>(out_f + f) = o;
            } else if (f < out_cap) {
                out_f[f] = re;
            }
        }
    }
}

extern "C" void kernel_launch(void* const* d_in, const int* in_sizes, int n_in,
                              void* d_out, int out_size) {
    if (n_in < 6) return;

    long long small = in_sizes[0];
    for (int i = 1; i < n_in; i++)
        if ((long long)in_sizes[i] < small) small = in_sizes[i];

    const float* big_ptrs[8];   int n_big = 0;
    long long big_sz = small;
    const float* small_ptrs[8]; int n_small = 0;
    for (int i = 0; i < n_in && i < 8; i++) {
        if ((long long)in_sizes[i] == small) {
            small_ptrs[n_small++] = (const float*)d_in[i];
        } else {
            big_ptrs[n_big++] = (const float*)d_in[i];
            big_sz = in_sizes[i];
        }
    }
    if (n_big != 2 || n_small != 4) return;

    long long B_ll = big_sz / small;
    if (B_ll < 1 || B_ll > 65536 || small < 1) return;
    int n = (int)small;
    int B = (int)B_ll;

    const float* x_real = big_ptrs[0];
    const float* x_imag = big_ptrs[1];
    const float* g_rr = small_ptrs[0];
    const float* g_ri = small_ptrs[1];
    const float* g_ii = small_ptrs[2];
    const float* bt   = small_ptrs[3];
    float* out_f = (float*)d_out;
    long long out_cap = (long long)out_size;

    int mode = (out_cap == big_sz) ? 0 : 1;
    int threads = 256;

    if (B == 16 && mode == 0 && out_cap >= big_sz && (n % 4) == 0) {
        int n4 = n / 4;
        int blocks = (n4 + threads - 1) / threads;
        cbn_b16_h_kernel<<<blocks, threads>>>(
            (const float2*)x_real, (const float2*)x_imag,
            (const float2*)g_rr, (const float2*)g_ri, (const float2*)bt,
            (float4*)out_f, n4);
    } else if (B == 16 && mode == 0 && out_cap >= big_sz && (n % 2) == 0) {
        int n2 = n / 2;
        int blocks = (n2 + threads - 1) / threads;
        cbn_b16_v2_kernel<<<blocks, threads>>>(
            (const float2*)x_real, (const float2*)x_imag,
            (const float2*)g_rr, (const float2*)g_ri, (const float2*)bt,
            (float2*)out_f, n2);
    } else {
        int blocks = (n + threads - 1) / threads;
        if (mode == 0)
            cbn_gen_kernel<0><<<blocks, threads>>>(x_real, x_imag,
                g_rr, g_ri, g_ii, bt, out_f, n, B, out_cap);
        else
            cbn_gen_kernel<1><<<blocks, threads>>>(x_real, x_imag,
                g_rr, g_ri, g_ii, bt, out_f, n, B, out_cap);
    }
}

// round 15
// speedup vs baseline: 1.3122x; 1.3122x over previous
#include <cuda_runtime.h>

// Complex BatchNorm, B=16 fast path, OUTPUT = float32 REAL PART ONLY.
// FINAL — reproduced 3x at 66.0-66.3us (kernel 59.5-60.4us, DRAM 81-82%,
// 6.4-6.5 TB/s = measured mixed-stream HBM roofline for 2:1 R/W traffic).
//   float2 vectorized, 2 positions/thread, all 16 batch samples (re+im) in
//   registers (128 regs -> 2 CTAs/SM), flat grid, default caching.
// Complete evidence sweep (DRAM% of peak):
//   32-bit scalar 71 | 128-bit flat 71 | 128-bit split 67.5 |
//   asm-hybrid 64/128 61 | **64-bit flat 81-82 (this kernel)**
//   occupancy 12-46% -> no BW effect; streaming hints -8% ; persistent -4%;
//   asm-pinned loads defeat ptxas MLP batching (R14).
//   g_ii unused for real-only output -> never loaded.

#define EPS 1e-5f

__global__ __launch_bounds__(256) void cbn_b16_v2_kernel(
    const float2* __restrict__ x_real,
    const float2* __restrict__ x_imag,
    const float2* __restrict__ g_rr,
    const float2* __restrict__ g_ri,
    const float2* __restrict__ beta,
    float2* __restrict__ out,
    int n2)   // n/2
{
    int idx = blockIdx.x * blockDim.x + threadIdx.x;
    if (idx >= n2) return;

    float2 rv[16], iv[16];
    #pragma unroll
    for (int b = 0; b < 16; b++) {
        rv[b] = x_real[(size_t)b * n2 + idx];
        iv[b] = x_imag[(size_t)b * n2 + idx];
    }

    float2 grr2 = g_rr[idx];
    float2 gri2 = g_ri[idx];
    float2 bt2  = beta[idx];

    const float inv_b = 1.0f / 16.0f;

    #pragma unroll
    for (int lane = 0; lane < 2; lane++) {
        float sr = 0.f, si = 0.f;
        #pragma unroll
        for (int b = 0; b < 16; b++) {
            sr += ((const float*)&rv[b])[lane];
            si += ((const float*)&iv[b])[lane];
        }
        float mu_r = sr * inv_b, mu_i = si * inv_b;

        float vrr = 0.f, vii = 0.f, vri = 0.f;
        #pragma unroll
        for (int b = 0; b < 16; b++) {
            float rc = ((const float*)&rv[b])[lane] - mu_r;
            float ic = ((const float*)&iv[b])[lane] - mu_i;
            vrr = fmaf(rc, rc, vrr);
            vii = fmaf(ic, ic, vii);
            vri = fmaf(rc, ic, vri);
        }
        vrr = vrr * inv_b + EPS;
        vii = vii * inv_b + EPS;
        vri = vri * inv_b;

        float tau = vrr + vii;
        float s   = sqrtf(fmaf(vrr, vii, -vri * vri));
        float t   = sqrtf(tau + 2.0f * s);
        float inv_st = 1.0f / (s * t);
        float wrr = (vii + s) * inv_st;
        float wii = (vrr + s) * inv_st;
        float wri = -vri * inv_st;

        float grr = ((const float*)&grr2)[lane];
        float gri = ((const float*)&gri2)[lane];
        float bt  = ((const float*)&bt2)[lane];

        #pragma unroll
        for (int b = 0; b < 16; b++) {
            float rc = ((const float*)&rv[b])[lane] - mu_r;
            float ic = ((const float*)&iv[b])[lane] - mu_i;
            float nr = fmaf(wrr, rc, wri * ic);
            float ni = fmaf(wii, ic, wri * rc);
            ((float*)&rv[b])[lane] = fmaf(grr, nr, fmaf(gri, ni, bt));
        }
    }

    #pragma unroll
    for (int b = 0; b < 16; b++)
        out[(size_t)b * n2 + idx] = rv[b];
}

// ---------- fallback paths (generic B / MODE 1 / ragged n) ----------

template <int MODE>
__global__ __launch_bounds__(256) void cbn_gen_kernel(
    const float* __restrict__ x_real,
    const float* __restrict__ x_imag,
    const float* __restrict__ g_rr,
    const float* __restrict__ g_ri,
    const float* __restrict__ g_ii,
    const float* __restrict__ beta,
    float* __restrict__ out_f,
    int n, int B, long long out_cap)
{
    int idx = blockIdx.x * blockDim.x + threadIdx.x;
    if (idx >= n) return;

    float sr = 0.f, si = 0.f, srr = 0.f, sii = 0.f, sri = 0.f;
    for (int b = 0; b < B; b++) {
        float rvv = x_real[(size_t)b * n + idx];
        float ivv = x_imag[(size_t)b * n + idx];
        sr += rvv; si += ivv;
        srr = fmaf(rvv, rvv, srr);
        sii = fmaf(ivv, ivv, sii);
        sri = fmaf(rvv, ivv, sri);
    }
    float inv_b = 1.0f / (float)B;
    float mu_r = sr * inv_b, mu_i = si * inv_b;
    float vrr = srr * inv_b - mu_r * mu_r + EPS;
    float vii = sii * inv_b - mu_i * mu_i + EPS;
    float vri = sri * inv_b - mu_r * mu_i;

    float s   = sqrtf(fmaf(vrr, vii, -vri * vri));
    float t   = sqrtf(vrr + vii + 2.0f * s);
    float inv_st = 1.0f / (s * t);
    float wrr = (vii + s) * inv_st;
    float wii = (vrr + s) * inv_st;
    float wri = -vri * inv_st;

    float grr = g_rr[idx], gri = g_ri[idx], gii = g_ii[idx], bt = beta[idx];

    for (int b = 0; b < B; b++) {
        float rc = x_real[(size_t)b * n + idx] - mu_r;
        float ic = x_imag[(size_t)b * n + idx] - mu_i;
        float nr = fmaf(wrr, rc, wri * ic);
        float ni = fmaf(wii, ic, wri * rc);
        float re = fmaf(grr, nr, fmaf(gri, ni, bt));
        long long j = (long long)b * n + idx;
        if (MODE == 0) {
            if (j < out_cap) out_f[j] = re;
        } else {
            float ie = fmaf(gri, nr, fmaf(gii, ni, bt));
            long long f = 2 * j;
            if (f + 1 < out_cap) {
                float2 o; o.x = re; o.y = ie;
                *reinterpret_cast<float2*>(out_f + f) = o;
            } else if (f < out_cap) {
                out_f[f] = re;
            }
        }
    }
}

extern "C" void kernel_launch(void* const* d_in, const int* in_sizes, int n_in,
                              void* d_out, int out_size) {
    if (n_in < 6) return;

    long long small = in_sizes[0];
    for (int i = 1; i < n_in; i++)
        if ((long long)in_sizes[i] < small) small = in_sizes[i];

    const float* big_ptrs[8];   int n_big = 0;
    long long big_sz = small;
    const float* small_ptrs[8]; int n_small = 0;
    for (int i = 0; i < n_in && i < 8; i++) {
        if ((long long)in_sizes[i] == small) {
            small_ptrs[n_small++] = (const float*)d_in[i];
        } else {
            big_ptrs[n_big++] = (const float*)d_in[i];
            big_sz = in_sizes[i];
        }
    }
    if (n_big != 2 || n_small != 4) return;

    long long B_ll = big_sz / small;
    if (B_ll < 1 || B_ll > 65536 || small < 1) return;
    int n = (int)small;
    int B = (int)B_ll;

    const float* x_real = big_ptrs[0];
    const float* x_imag = big_ptrs[1];
    const float* g_rr = small_ptrs[0];
    const float* g_ri = small_ptrs[1];
    const float* g_ii = small_ptrs[2];
    const float* bt   = small_ptrs[3];
    float* out_f = (float*)d_out;
    long long out_cap = (long long)out_size;

    int mode = (out_cap == big_sz) ? 0 : 1;

    int threads = 256;

    if (B == 16 && mode == 0 && (n % 2) == 0 && out_cap >= big_sz) {
        int n2 = n / 2;
        int blocks = (n2 + threads - 1) / threads;
        cbn_b16_v2_kernel<<<blocks, threads>>>(
            (const float2*)x_real, (const float2*)x_imag,
            (const float2*)g_rr, (const float2*)g_ri, (const float2*)bt,
            (float2*)out_f, n2);
    } else {
        int blocks = (n + threads - 1) / threads;
        if (mode == 0)
            cbn_gen_kernel<0><<<blocks, threads>>>(x_real, x_imag,
                g_rr, g_ri, g_ii, bt, out_f, n, B, out_cap);
        else
            cbn_gen_kernel<1><<<blocks, threads>>>(x_real, x_imag,
                g_rr, g_ri, g_ii, bt, out_f, n, B, out_cap);
    }
}